// round 17
// baseline (speedup 1.0000x reference)
#include <cuda_runtime.h>

// ConvCNP via 1-D Fast Gauss Transform (Hermite, P=16), SINGLE fused kernel,
// single wave. 512 blocks @ __launch_bounds__(256,4) => regs<=62 => 4 blocks/SM
// => all blocks co-resident (R11's failure was 104 regs => 2 waves).
// Blocks 0..63 first compute coefficients for (batch, box-slot) and release
// via fenced atomicAdd on per-batch padded counters; every block then waits
// (tid0 ld.acquire + __nanosleep backoff) for ITS batch, stages coefficients,
// and evaluates one 64-target tile. Counters self-reset per batch.
//
//   density(t) = sum_n exp(-(u_n-t)^2/d0),  d_c = 2*exp(2*sigma_c)
//   num(t)     = sum_n w_n exp(-(u_n-t)^2/d1)
//   out[b,m,:] = [density, num/(density+1e-8)] @ W.T + bias
//
// h_{k+1} = 2x h_k - 2k h_{k-1}; boxes of width sqrt(delta_min) => |z|<=0.5;
// truncation at P=16 ~8.5e-10/source (rel ~1e-8, verified unchanged rel_err).
// Brute-force fallback if nbox > MAXBOX.

#define BATCH  4
#define NCTX   2048
#define MTGT   8192
#define NOUT   64
#define P      16
#define NW     (2 * P)              // 32 words per (b,box)
#define MAXBOX 64
#define CSLOTS 16                   // coef box-slots per batch
#define NCOEFB (BATCH * CSLOTS)     // 64 coef-role blocks
#define BLOCK  256
#define TTILE  64
#define TPB    (MTGT / TTILE)       // 128 eval blocks per batch
#define GRID   (BATCH * TPB)        // 512 blocks
#define XMIN   (-8.0f)
#define XRANGE 16.0f
#define SQRT2  1.41421356237f
#define LOG2E  1.44269504089f

struct alignas(128) PadCtr { unsigned v; unsigned pad[31]; };

__device__ float  g_coef[BATCH * MAXBOX * NW];
__device__ PadCtr g_cdone[BATCH];   // coef arrivals per batch (one line each)
__device__ PadCtr g_edone[BATCH];   // eval completions per batch (for reset)

__constant__ float c_invfact[P] = {
    1.0f, 1.0f, 0.5f, 1.6666667e-1f, 4.1666667e-2f,
    8.3333333e-3f, 1.3888889e-3f, 1.9841270e-4f, 2.4801587e-5f, 2.7557319e-6f,
    2.7557319e-7f, 2.5052108e-8f, 2.0876757e-9f, 1.6059044e-10f, 1.1470746e-11f,
    7.6471637e-13f
};

__device__ __forceinline__ float ex2f(float x) {
    float y; asm("ex2.approx.f32 %0, %1;" : "=f"(y) : "f"(x)); return y;
}
__device__ __forceinline__ unsigned ld_acquire(const unsigned* p) {
    unsigned v;
    asm volatile("ld.acquire.gpu.u32 %0, [%1];" : "=r"(v) : "l"(p));
    return v;
}

__global__ __launch_bounds__(BLOCK, 4) void convcnp_fused(
    const float* __restrict__ context_in,    // [B, N]
    const float* __restrict__ context_out,   // [B, N]
    const float* __restrict__ target_in,     // [B, M]
    const float* __restrict__ sigma,         // [2]
    const float* __restrict__ W,             // [64, 2]
    const float* __restrict__ bias,          // [64]
    float* __restrict__ out)                 // [B, M, 64]
{
    __shared__ float  s_red[BLOCK / 32][NW + 1];
    __shared__ float4 s_coef4[MAXBOX * NW / 4];   // 8 KB
    __shared__ float2 s_res[TTILE];

    const int tid  = threadIdx.x;
    const int bid  = blockIdx.x;
    const int lane = tid & 31, wrp = tid >> 5;

    // Eval-tile identity.
    const int b2 = bid >> 7;                 // / TPB
    const int m0 = (bid & (TPB - 1)) * TTILE;

    // Independent prologue loads.
    const float t = target_in[b2 * MTGT + m0 + (tid & (TTILE - 1))];
    const int j0 = (tid & 15) * 4;
    float W0[4], W1[4], bb[4];
    #pragma unroll
    for (int q = 0; q < 4; q++) {
        W0[q] = W[(j0 + q) * 2 + 0];
        W1[q] = W[(j0 + q) * 2 + 1];
        bb[q] = bias[j0 + q];
    }

    // Geometry from sigma (every block; one L2-hot line).
    const float s0 = __expf(sigma[0]), s1 = __expf(sigma[1]);
    const float sd0 = s0 * SQRT2, sd1 = s1 * SQRT2;      // sqrt(delta_c)
    const float wbox = fminf(sd0, sd1);
    const int   nbox = (int)ceilf(XRANGE / wbox);
    const bool  fgt_ok = (nbox <= MAXBOX);
    const float isd0 = 1.0f / sd0, isd1 = 1.0f / sd1;

    // Eval Horner arguments (pre-release, independent of coefficients).
    int bi = (int)floorf((t - XMIN) / wbox);
    bi = max(0, min(nbox - 1, bi));
    const float cb = XMIN + (bi + 0.5f) * wbox;
    const float z0 = (t - cb) * isd0;
    const float z1 = (t - cb) * isd1;

    // ================= Coef role: blocks 0..63 =================
    if (bid < NCOEFB) {
        const int b    = bid >> 4;           // batch this block computes for
        const int slot = bid & (CSLOTS - 1);
        if (fgt_ok && slot < nbox) {
            const float* __restrict__ uin = context_in  + b * NCTX;
            const float* __restrict__ win = context_out + b * NCTX;
            const bool eqscale = (sd0 == sd1);

            for (int box = slot; box < nbox; box += CSLOTS) {
                const float cbox = XMIN + (box + 0.5f) * wbox;
                float r[NW];
                #pragma unroll
                for (int k = 0; k < NW; k++) r[k] = 0.0f;

                if (eqscale) {
                    // Equal scales: one recurrence feeds both channels.
                    // u/w loaded per point (L1-hot after the first box);
                    // no register prefetch array — keeps regs under the
                    // single-wave cap.
                    for (int n = tid; n < NCTX; n += BLOCK) {
                        const float u = uin[n], w = win[n];
                        const float tt = (u - cbox) * isd0;
                        const float h0 = ex2f(-tt * tt * LOG2E);
                        const float t2 = tt + tt;
                        float hm = h0, hc = t2 * h0;
                        r[0] += h0;  r[P]     = fmaf(w, h0, r[P]);
                        r[1] += hc;  r[P + 1] = fmaf(w, hc, r[P + 1]);
                        #pragma unroll
                        for (int k = 1; k < P - 1; k++) {
                            const float hn = fmaf(t2, hc, -(2.0f * k) * hm);
                            r[k + 1] += hn;  r[P + k + 1] = fmaf(w, hn, r[P + k + 1]);
                            hm = hc; hc = hn;
                        }
                    }
                } else {
                    for (int n = tid; n < NCTX; n += BLOCK) {
                        const float u = uin[n], w = win[n];
                        {
                            const float tt = (u - cbox) * isd0;
                            const float h0 = ex2f(-tt * tt * LOG2E);
                            const float t2 = tt + tt;
                            float hm = h0, hc = t2 * h0;
                            r[0] += h0; r[1] += hc;
                            #pragma unroll
                            for (int k = 1; k < P - 1; k++) {
                                const float hn = fmaf(t2, hc, -(2.0f * k) * hm);
                                r[k + 1] += hn; hm = hc; hc = hn;
                            }
                        }
                        {
                            const float tt = (u - cbox) * isd1;
                            const float h0 = ex2f(-tt * tt * LOG2E);
                            const float t2 = tt + tt;
                            float hm = h0, hc = t2 * h0;
                            r[P] = fmaf(w, h0, r[P]); r[P + 1] = fmaf(w, hc, r[P + 1]);
                            #pragma unroll
                            for (int k = 1; k < P - 1; k++) {
                                const float hn = fmaf(t2, hc, -(2.0f * k) * hm);
                                r[P + k + 1] = fmaf(w, hn, r[P + k + 1]); hm = hc; hc = hn;
                            }
                        }
                    }
                }

                // Split-butterfly: 31 shuffles reduce all 32 values; lane l
                // ends holding the warp-sum of value l.
                #pragma unroll
                for (int s = 16; s >= 1; s >>= 1) {
                    const bool up = (lane & s) != 0;
                    #pragma unroll
                    for (int i = 0; i < s; i++) {
                        const float send  = up ? r[i] : r[i + s];
                        const float other = __shfl_xor_sync(0xffffffffu, send, s);
                        const float keep  = up ? r[i + s] : r[i];
                        r[i] = keep + other;
                    }
                }
                s_red[wrp][lane] = r[0];
                __syncthreads();
                if (tid < NW) {
                    float v = 0.0f;
                    #pragma unroll
                    for (int ww = 0; ww < BLOCK / 32; ww++) v += s_red[ww][tid];
                    g_coef[(b * MAXBOX + box) * NW + tid] = v * c_invfact[tid & (P - 1)];
                }
                __syncthreads();
            }
        }
        // Release (unconditional, incl. idle slots and brute-force path):
        // CTA-sync orders all warps' stores before tid0's fenced arrival.
        __syncthreads();
        if (tid == 0) {
            __threadfence();
            atomicAdd(&g_cdone[b].v, 1u);
        }
    }

    // ================= Eval role: all 512 blocks =================
    float den = 0.0f, num = 0.0f;
    if (fgt_ok) {
        // Wait for THIS batch's 16 coef blocks (acquire + nanosleep backoff).
        if (tid == 0) {
            while (ld_acquire(&g_cdone[b2].v) < CSLOTS) __nanosleep(64);
        }
        __syncthreads();

        // Stage all MAXBOX coefficient rows (fixed trip, coalesced, coherent).
        {
            const float4* src = (const float4*)g_coef + b2 * (MAXBOX * NW / 4);
            #pragma unroll
            for (int i = 0; i < (MAXBOX * NW / 4) / BLOCK; i++)   // 2 per thread
                s_coef4[tid + i * BLOCK] = src[tid + i * BLOCK];
        }
        __syncthreads();

        if (tid < TTILE) {
            float c[NW];
            const float4* __restrict__ cf = s_coef4 + bi * (NW / 4);
            #pragma unroll
            for (int i = 0; i < NW / 4; i++) {
                const float4 v = cf[i];
                c[i * 4 + 0] = v.x; c[i * 4 + 1] = v.y;
                c[i * 4 + 2] = v.z; c[i * 4 + 3] = v.w;
            }
            den = c[P - 1];
            num = c[NW - 1];
            #pragma unroll
            for (int k = P - 2; k >= 0; k--) {
                den = fmaf(den, z0, c[k]);
                num = fmaf(num, z1, c[P + k]);
            }
            s_res[tid] = make_float2(den, num / (den + 1e-8f));
        }
    } else {
        // Brute-force fallback (exotic sigma; uniform branch).
        if (tid < TTILE) {
            const float k0c = -0.5f * LOG2E / (s0 * s0);
            const float k1c = -0.5f * LOG2E / (s1 * s1);
            const float* __restrict__ uin = context_in  + b2 * NCTX;
            const float* __restrict__ win = context_out + b2 * NCTX;
            for (int n = 0; n < NCTX; n++) {
                const float u = __ldg(&uin[n]), w = __ldg(&win[n]);
                const float d = u - t, s = d * d;
                den += ex2f(s * k0c);
                num = fmaf(w, ex2f(s * k1c), num);
            }
            s_res[tid] = make_float2(den, num / (den + 1e-8f));
        }
    }
    __syncthreads();

    // Epilogue: 64 targets x 64 channels = 1024 float4 stores, coalesced.
    float4* __restrict__ outp = (float4*)(out + ((long)b2 * MTGT + m0) * NOUT);
    #pragma unroll
    for (int k = 0; k < 4; k++) {
        const int idx4 = tid + k * BLOCK;    // 0..1023
        const float2 r = s_res[idx4 >> 4];
        float4 v;
        v.x = fmaf(r.x, W0[0], fmaf(r.y, W1[0], bb[0]));
        v.y = fmaf(r.x, W0[1], fmaf(r.y, W1[1], bb[1]));
        v.z = fmaf(r.x, W0[2], fmaf(r.y, W1[2], bb[2]));
        v.w = fmaf(r.x, W0[3], fmaf(r.y, W1[3], bb[3]));
        outp[idx4] = v;
    }

    // ================= Counter reset (graph-replay determinism) =================
    // Last of this batch's 128 eval blocks resets both counters; it first
    // confirms all 16 coef arrivals landed (covers the brute-force path,
    // where evals never spin on g_cdone).
    __syncthreads();
    if (tid == 0) {
        __threadfence();
        const unsigned old = atomicAdd(&g_edone[b2].v, 1u);
        if (old == TPB - 1) {
            while (ld_acquire(&g_cdone[b2].v) < CSLOTS) __nanosleep(64);
            g_cdone[b2].v = 0u;
            g_edone[b2].v = 0u;
            __threadfence();
        }
    }
}

extern "C" void kernel_launch(void* const* d_in, const int* in_sizes, int n_in,
                              void* d_out, int out_size) {
    const float* context_in  = (const float*)d_in[0];
    const float* context_out = (const float*)d_in[1];
    const float* target_in   = (const float*)d_in[2];
    const float* sigma       = (const float*)d_in[3];
    const float* W           = (const float*)d_in[4];
    const float* bias        = (const float*)d_in[5];
    float* out = (float*)d_out;

    convcnp_fused<<<GRID, BLOCK>>>(context_in, context_out, target_in,
                                   sigma, W, bias, out);
}